// round 15
// baseline (speedup 1.0000x reference)
#include <cuda_runtime.h>
#include <cstdint>
#include <cstddef>
#include <math_constants.h>

#define B_    2
#define C_    256
#define H_    512
#define W_    512
#define PS    52
#define NH    9
#define NW    9
#define P_    81
#define QQ    2704         // PS*PS
#define PLANE (H_*W_)      // 262144

#define SBS   132          // staging stride (mult of 4; +XOR swizzle)

// Scratch (device globals: no allocations allowed)
__device__ float d_gp[B_*P_*256];       // per (b,pp) per-channel sums (covered)
__device__ float d_gb2[B_*C_*2];        // per-plane border sums (2 partials)
__device__ float d_S16[B_*P_*16*256];   // per (b,pp,cg) partial weighted sums
__device__ float d_Q16[B_*P_*16];       // per (b,pp,cg) partial sumsq
__device__ float d_cos[B_*P_];

__device__ __forceinline__ float warpReduce(float v) {
  #pragma unroll
  for (int o = 16; o > 0; o >>= 1) v += __shfl_down_sync(0xffffffffu, v, o);
  return v;
}

__device__ __forceinline__ int swz(int kw) {   // XOR swizzle, mult of 4
  return ((kw + (kw >> 2)) & 7) << 2;
}

__device__ __forceinline__ void cp16(uint32_t saddr, const void* gaddr) {
  asm volatile("cp.async.cg.shared.global [%0], [%1], 16;\n"
               :: "r"(saddr), "l"(gaddr));
}

// ------------------------------------------- per-patch stats (covered region)
// Block = (b, pp, channel-group of 16). 4 lane-groups of 64; lane u of group g
// owns bins 4u..4u+3: for channel c it reads float4 at q = ((4u-144c)&255)
// + 256*j (widx of element q+k is 4u+k; kw == 0 mod 4 so the float4 never
// crosses a source row). Group g handles channels cg*16 + g*4 + cc. Bins
// accumulate in registers -> smem merge. No atomics anywhere.
#define CG 16
__global__ __launch_bounds__(256) void k_stats(const float* __restrict__ x) {
  __shared__ float4 sb4[4 * 64];     // [group][u] bins 4u..4u+3
  __shared__ float qred[8];
  __shared__ float sm_g[8 * 4];      // [warp][cc] per-warp channel partials
  int bid = blockIdx.x;
  int cg = bid & 15;                 // C_/CG == 16 groups
  int pp = (bid >> 4) % P_;
  int b  = bid / (16 * P_);
  int ph = pp / NW, pw = pp - ph * NW;
  int t = threadIdx.x;
  int lane = t & 31, warp = t >> 5;
  int g = t >> 6;                    // lane-group 0..3
  int u = t & 63;                    // 0..63, owns bins 4u..4u+3

  const float* pbase = x + (size_t)b * C_ * PLANE + (size_t)(ph * PS) * W_ + pw * PS;

  float a0 = 0.f, a1 = 0.f, a2 = 0.f, a3 = 0.f;  // bins 4u..4u+3
  float qacc = 0.f;                               // sum of squares
  #pragma unroll 1
  for (int cc = 0; cc < 4; ++cc) {
    int c = cg * CG + g * 4 + cc;
    const float* cb = pbase + (size_t)c * PLANE;
    int q0 = (4 * u - 144 * c) & 255;
    float csum = 0.f;
    #pragma unroll
    for (int j = 0; j < 11; ++j) {
      int q = q0 + 256 * j;
      if (q < QQ) {
        int kh = q / PS;
        int kw = q - kh * PS;
        float4 v = *reinterpret_cast<const float4*>(cb + kh * W_ + kw);
        a0 += v.x; a1 += v.y; a2 += v.z; a3 += v.w;
        csum += (v.x + v.y) + (v.z + v.w);
        qacc = fmaf(v.x, v.x, qacc);
        qacc = fmaf(v.y, v.y, qacc);
        qacc = fmaf(v.z, v.z, qacc);
        qacc = fmaf(v.w, v.w, qacc);
      }
    }
    csum = warpReduce(csum);
    if (lane == 0) sm_g[warp * 4 + cc] = csum;   // two warps per group
  }
  sb4[g * 64 + u] = make_float4(a0, a1, a2, a3);

  qacc = warpReduce(qacc);
  if (lane == 0) qred[warp] = qacc;
  __syncthreads();

  // merge the 4 group-copies of bin t and store
  const float* sb = reinterpret_cast<const float*>(sb4);
  float S = sb[t] + sb[256 + t] + sb[512 + t] + sb[768 + t];
  d_S16[((size_t)(b * P_ + pp) * 16 + cg) * 256 + t] = S;

  if (t < 16) {                      // channel c = cg*16 + t, t = g*4+cc
    int gg = t >> 2, cc = t & 3;
    float cs2 = sm_g[(2 * gg) * 4 + cc] + sm_g[(2 * gg + 1) * 4 + cc];
    d_gp[(b * P_ + pp) * 256 + cg * 16 + t] = cs2;  // unique writer
  }
  if (warp == 0) {
    float v = (lane < 8) ? qred[lane] : 0.f;
    v = warpReduce(v);
    if (lane == 0) d_Q16[(b * P_ + pp) * 16 + cg] = v;
  }
}

// -------------------------------------------------- GAP over uncovered border
__global__ __launch_bounds__(256) void k_border_g(const float* __restrict__ x) {
  int plane = blockIdx.y;                    // 0..B_*C_-1
  int half = blockIdx.x;                     // 0..1
  const float* pb = x + (size_t)plane * PLANE;
  float s = 0.f;
  #pragma unroll 4
  for (int j = half * 256 + threadIdx.x; j < 43120; j += 512) {
    int r, col;
    if (j < 20592) { r = j / 44; col = 468 + (j - r * 44); }
    else           { int j2 = j - 20592; r = 468 + (j2 >> 9); col = j2 & 511; }
    s += pb[(size_t)r * W_ + col];
  }
  __shared__ float red[8];
  int lane = threadIdx.x & 31, warp = threadIdx.x >> 5;
  s = warpReduce(s);
  if (lane == 0) red[warp] = s;
  __syncthreads();
  if (warp == 0) {
    float v = (lane < 8) ? red[lane] : 0.f;
    v = warpReduce(v);
    if (lane == 0) d_gb2[plane * 2 + half] = v;
  }
}

// --------------------------------------------- cosine per patch (grid 2*81)
__global__ __launch_bounds__(256) void k_cos() {
  int bp = blockIdx.x;               // b*81 + pp
  int b = bp / P_;
  int t = threadIdx.x;
  int lane = t & 31, warp = t >> 5;

  float gs = d_gb2[(b * C_ + t) * 2] + d_gb2[(b * C_ + t) * 2 + 1];
  const float* gp = d_gp + (size_t)b * P_ * 256 + t;
  #pragma unroll
  for (int i = 0; i < P_; ++i) gs += gp[i * 256];
  float g = gs * (1.0f / (float)PLANE);

  float s = 0.f;
  const float* Sp = d_S16 + (size_t)bp * 16 * 256 + t;
  #pragma unroll
  for (int cg = 0; cg < 16; ++cg) s += Sp[cg * 256];

  float dotv = s * g;
  float gg = g * g;
  __shared__ float rd[8], rg[8];
  dotv = warpReduce(dotv);
  gg = warpReduce(gg);
  if (lane == 0) { rd[warp] = dotv; rg[warp] = gg; }
  __syncthreads();
  if (t == 0) {
    float D = 0.f, G = 0.f;
    #pragma unroll
    for (int i = 0; i < 8; ++i) { D += rd[i]; G += rg[i]; }
    float q = 0.f;
    const float* Qp = d_Q16 + bp * 16;
    #pragma unroll
    for (int i = 0; i < 16; ++i) q += Qp[i];
    float gnorm = sqrtf(G) * (float)PS;
    float pnorm = sqrtf(q);
    d_cos[bp] = D / fmaxf(gnorm * pnorm, 1e-8f);
  }
}

// ------------------------------------------------------- apply mask (covered)
// Block = (b, pp, kh, channel-half of 128). Warp 0 computes argmax/argmin of
// cos to pick the source patch. Phase 1: gather via cp.async.cg into swizzled
// smem (no regs, L1 bypass). Phase 2: sub-loop A issues all 4 independent
// multiplicand LDG.128 (uint32 offsets), sub-loop B does LDS+FFMA+STG.
// launch_bounds(512,4) caps regs at 32 -> 4 blocks/SM (64 warps).
__global__ __launch_bounds__(512, 4) void k_apply(const float* __restrict__ x,
                                                  float* __restrict__ out) {
  __shared__ float sbuf[PS * SBS];   // 27.5 KB
  __shared__ int s_sp;
  int lin = blockIdx.x;
  int chalf = lin & 1;
  int kh = (lin >> 1) % PS;
  int pp = ((lin >> 1) / PS) % P_;
  int b  = lin / (2 * PS * P_);
  int ph = pp / NW, pw = pp - ph * NW;
  int t = threadIdx.x;
  int c0 = chalf * 128;

  if (t < 32) {                      // warp 0: argmax/argmin over 81 cos
    int lane = t;
    float vmax = -CUDART_INF_F, vmin = CUDART_INF_F;
    int imax = -1, imin = -1;
    #pragma unroll
    for (int k = 0; k < 3; ++k) {
      int i = lane + 32 * k;
      if (i < P_) {
        float cv = d_cos[b * P_ + i];
        if (cv > vmax || (cv == vmax && i < imax)) { vmax = cv; imax = i; }
        if (cv < vmin || (cv == vmin && i < imin)) { vmin = cv; imin = i; }
      }
    }
    #pragma unroll
    for (int o = 16; o > 0; o >>= 1) {
      float ov = __shfl_down_sync(0xffffffffu, vmax, o);
      int   oi = __shfl_down_sync(0xffffffffu, imax, o);
      if (ov > vmax || (ov == vmax && oi < imax)) { vmax = ov; imax = oi; }
      float nv = __shfl_down_sync(0xffffffffu, vmin, o);
      int   ni = __shfl_down_sync(0xffffffffu, imin, o);
      if (nv < vmin || (nv == vmin && ni < imin)) { vmin = nv; imin = ni; }
    }
    if (lane == 0) s_sp = (pp == imax) ? imin : pp;
  }
  __syncthreads();
  int sp = s_sp;
  int sph = sp / NW, spw = sp - sph * NW;

  const float* xb = x + (size_t)b * C_ * PLANE;
  const float* src = xb + (size_t)(sph * PS) * W_ + spw * PS;
  int mbase = kh * PS * 256 + c0;
  int h  = ph * PS + kh;
  int wb = pw * PS;
  uint32_t sb_u32 = (uint32_t)__cvta_generic_to_shared(sbuf);

  // Phase 1: gather 1664 float4 via cp.async (source-linear, coalesced;
  // m = mbase + i is consecutive source addresses, no row/chan straddle)
  #pragma unroll
  for (int k = 0; k < 4; ++k) {
    int i4 = t + 512 * k;
    if (i4 < 1664) {
      int i = i4 << 2;
      int kw = i >> 7;
      int cl = i & 127;
      int m = mbase + kw * 256 + cl;
      int cs  = m / QQ;
      int r   = m - cs * QQ;
      int khs = r / PS;
      int kws = r - khs * PS;
      int si = kw * SBS + (cl ^ swz(kw));
      cp16(sb_u32 + (si << 2), src + (size_t)cs * PLANE + khs * W_ + kws);
    }
  }
  asm volatile("cp.async.commit_group;\n" ::: "memory");
  asm volatile("cp.async.wait_group 0;\n" ::: "memory");
  __syncthreads();

  // Phase 2a: batch the 4 independent multiplicand LDG.128
  uint32_t off32[4];
  float4 pre[4];
  #pragma unroll
  for (int k = 0; k < 4; ++k) {
    int i4 = t + 512 * k;
    if (i4 < 1664) {
      int col_ = i4 / 13;
      int kw0  = (i4 - col_ * 13) << 2;
      off32[k] = (uint32_t)(((b * C_ + c0 + col_) * H_ + h) * W_ + wb + kw0);
      pre[k] = *reinterpret_cast<const float4*>(x + off32[k]);
    }
  }
  // Phase 2b: smem reads + FFMA + coalesced float4 stores
  #pragma unroll
  for (int k = 0; k < 4; ++k) {
    int i4 = t + 512 * k;
    if (i4 < 1664) {
      int col_ = i4 / 13;
      int kw0  = (i4 - col_ * 13) << 2;
      float m0v = sbuf[(kw0    ) * SBS + (col_ ^ swz(kw0    ))];
      float m1v = sbuf[(kw0 + 1) * SBS + (col_ ^ swz(kw0 + 1))];
      float m2v = sbuf[(kw0 + 2) * SBS + (col_ ^ swz(kw0 + 2))];
      float m3v = sbuf[(kw0 + 3) * SBS + (col_ ^ swz(kw0 + 3))];
      float4 ov;
      ov.x = m0v * pre[k].x;
      ov.y = m1v * pre[k].y;
      ov.z = m2v * pre[k].z;
      ov.w = m3v * pre[k].w;
      *reinterpret_cast<float4*>(out + off32[k]) = ov;
    }
  }
}

// ------------------------------------------------------------ zero the border
__global__ __launch_bounds__(256) void k_border_out(float* __restrict__ out) {
  int plane = blockIdx.y;
  size_t pb = (size_t)plane * PLANE;
  float4 z = make_float4(0.f, 0.f, 0.f, 0.f);
  for (int i = blockIdx.x * blockDim.x + threadIdx.x; i < 10780;
       i += gridDim.x * blockDim.x) {
    size_t off;
    if (i < 5148) { int r = i / 11; int cq = i - r * 11;
                    off = pb + (size_t)r * W_ + 468 + (cq << 2); }
    else          { int j = i - 5148; int r = j >> 7; int cq = j & 127;
                    off = pb + (size_t)(468 + r) * W_ + (cq << 2); }
    *reinterpret_cast<float4*>(out + off) = z;
  }
}

extern "C" void kernel_launch(void* const* d_in, const int* in_sizes, int n_in,
                              void* d_out, int out_size) {
  (void)in_sizes; (void)n_in; (void)out_size;
  const float* x = (const float*)d_in[0];
  float* out = (float*)d_out;

  k_stats<<<B_ * P_ * 16, 256>>>(x);
  k_border_g<<<dim3(2, B_ * C_), 256>>>(x);
  k_cos<<<B_ * P_, 256>>>();
  k_apply<<<B_ * P_ * PS * 2, 512>>>(x, out);   // <- ncu capture slot (4th)
  k_border_out<<<dim3(11, B_ * C_), 256>>>(out);
}

// round 16
// speedup vs baseline: 1.0014x; 1.0014x over previous
#include <cuda_runtime.h>
#include <cstdint>
#include <cstddef>
#include <math_constants.h>

#define B_    2
#define C_    256
#define H_    512
#define W_    512
#define PS    52
#define NH    9
#define NW    9
#define P_    81
#define QQ    2704         // PS*PS
#define PLANE (H_*W_)      // 262144

#define SBS   132          // staging stride (mult of 4; +XOR swizzle)
#define STGF  (PS * SBS)   // floats per pipeline stage (6864 = 27.5 KB)

// Scratch (device globals: no allocations allowed)
__device__ float d_gp[B_*P_*256];       // per (b,pp) per-channel sums (covered)
__device__ float d_gb2[B_*C_*2];        // per-plane border sums (2 partials)
__device__ float d_S16[B_*P_*16*256];   // per (b,pp,cg) partial weighted sums
__device__ float d_Q16[B_*P_*16];       // per (b,pp,cg) partial sumsq
__device__ float d_cos[B_*P_];

__device__ __forceinline__ float warpReduce(float v) {
  #pragma unroll
  for (int o = 16; o > 0; o >>= 1) v += __shfl_down_sync(0xffffffffu, v, o);
  return v;
}

__device__ __forceinline__ int swz(int kw) {   // XOR swizzle, mult of 4
  return ((kw + (kw >> 2)) & 7) << 2;
}

__device__ __forceinline__ void cp16(uint32_t saddr, const void* gaddr) {
  asm volatile("cp.async.cg.shared.global [%0], [%1], 16;\n"
               :: "r"(saddr), "l"(gaddr));
}

// ------------------------------------------- per-patch stats (covered region)
// Block = (b, pp, channel-group of 16). 4 lane-groups of 64; lane u of group g
// owns bins 4u..4u+3: for channel c it reads float4 at q = ((4u-144c)&255)
// + 256*j (widx of element q+k is 4u+k; kw == 0 mod 4 so the float4 never
// crosses a source row). Group g handles channels cg*16 + g*4 + cc. Bins
// accumulate in registers -> smem merge. No atomics anywhere.
#define CG 16
__global__ __launch_bounds__(256) void k_stats(const float* __restrict__ x) {
  __shared__ float4 sb4[4 * 64];     // [group][u] bins 4u..4u+3
  __shared__ float qred[8];
  __shared__ float sm_g[8 * 4];      // [warp][cc] per-warp channel partials
  int bid = blockIdx.x;
  int cg = bid & 15;                 // C_/CG == 16 groups
  int pp = (bid >> 4) % P_;
  int b  = bid / (16 * P_);
  int ph = pp / NW, pw = pp - ph * NW;
  int t = threadIdx.x;
  int lane = t & 31, warp = t >> 5;
  int g = t >> 6;                    // lane-group 0..3
  int u = t & 63;                    // 0..63, owns bins 4u..4u+3

  const float* pbase = x + (size_t)b * C_ * PLANE + (size_t)(ph * PS) * W_ + pw * PS;

  float a0 = 0.f, a1 = 0.f, a2 = 0.f, a3 = 0.f;  // bins 4u..4u+3
  float qacc = 0.f;                               // sum of squares
  #pragma unroll 1
  for (int cc = 0; cc < 4; ++cc) {
    int c = cg * CG + g * 4 + cc;
    const float* cb = pbase + (size_t)c * PLANE;
    int q0 = (4 * u - 144 * c) & 255;
    float csum = 0.f;
    #pragma unroll
    for (int j = 0; j < 11; ++j) {
      int q = q0 + 256 * j;
      if (q < QQ) {
        int kh = q / PS;
        int kw = q - kh * PS;
        float4 v = *reinterpret_cast<const float4*>(cb + kh * W_ + kw);
        a0 += v.x; a1 += v.y; a2 += v.z; a3 += v.w;
        csum += (v.x + v.y) + (v.z + v.w);
        qacc = fmaf(v.x, v.x, qacc);
        qacc = fmaf(v.y, v.y, qacc);
        qacc = fmaf(v.z, v.z, qacc);
        qacc = fmaf(v.w, v.w, qacc);
      }
    }
    csum = warpReduce(csum);
    if (lane == 0) sm_g[warp * 4 + cc] = csum;   // two warps per group
  }
  sb4[g * 64 + u] = make_float4(a0, a1, a2, a3);

  qacc = warpReduce(qacc);
  if (lane == 0) qred[warp] = qacc;
  __syncthreads();

  // merge the 4 group-copies of bin t and store
  const float* sb = reinterpret_cast<const float*>(sb4);
  float S = sb[t] + sb[256 + t] + sb[512 + t] + sb[768 + t];
  d_S16[((size_t)(b * P_ + pp) * 16 + cg) * 256 + t] = S;

  if (t < 16) {                      // channel c = cg*16 + t, t = g*4+cc
    int gg = t >> 2, cc = t & 3;
    float cs2 = sm_g[(2 * gg) * 4 + cc] + sm_g[(2 * gg + 1) * 4 + cc];
    d_gp[(b * P_ + pp) * 256 + cg * 16 + t] = cs2;  // unique writer
  }
  if (warp == 0) {
    float v = (lane < 8) ? qred[lane] : 0.f;
    v = warpReduce(v);
    if (lane == 0) d_Q16[(b * P_ + pp) * 16 + cg] = v;
  }
}

// -------------------------------------------------- GAP over uncovered border
__global__ __launch_bounds__(256) void k_border_g(const float* __restrict__ x) {
  int plane = blockIdx.y;                    // 0..B_*C_-1
  int half = blockIdx.x;                     // 0..1
  const float* pb = x + (size_t)plane * PLANE;
  float s = 0.f;
  #pragma unroll 4
  for (int j = half * 256 + threadIdx.x; j < 43120; j += 512) {
    int r, col;
    if (j < 20592) { r = j / 44; col = 468 + (j - r * 44); }
    else           { int j2 = j - 20592; r = 468 + (j2 >> 9); col = j2 & 511; }
    s += pb[(size_t)r * W_ + col];
  }
  __shared__ float red[8];
  int lane = threadIdx.x & 31, warp = threadIdx.x >> 5;
  s = warpReduce(s);
  if (lane == 0) red[warp] = s;
  __syncthreads();
  if (warp == 0) {
    float v = (lane < 8) ? red[lane] : 0.f;
    v = warpReduce(v);
    if (lane == 0) d_gb2[plane * 2 + half] = v;
  }
}

// --------------------------------------------- cosine per patch (grid 2*81)
__global__ __launch_bounds__(256) void k_cos() {
  int bp = blockIdx.x;               // b*81 + pp
  int b = bp / P_;
  int t = threadIdx.x;
  int lane = t & 31, warp = t >> 5;

  float gs = d_gb2[(b * C_ + t) * 2] + d_gb2[(b * C_ + t) * 2 + 1];
  const float* gp = d_gp + (size_t)b * P_ * 256 + t;
  #pragma unroll
  for (int i = 0; i < P_; ++i) gs += gp[i * 256];
  float g = gs * (1.0f / (float)PLANE);

  float s = 0.f;
  const float* Sp = d_S16 + (size_t)bp * 16 * 256 + t;
  #pragma unroll
  for (int cg = 0; cg < 16; ++cg) s += Sp[cg * 256];

  float dotv = s * g;
  float gg = g * g;
  __shared__ float rd[8], rg[8];
  dotv = warpReduce(dotv);
  gg = warpReduce(gg);
  if (lane == 0) { rd[warp] = dotv; rg[warp] = gg; }
  __syncthreads();
  if (t == 0) {
    float D = 0.f, G = 0.f;
    #pragma unroll
    for (int i = 0; i < 8; ++i) { D += rd[i]; G += rg[i]; }
    float q = 0.f;
    const float* Qp = d_Q16 + bp * 16;
    #pragma unroll
    for (int i = 0; i < 16; ++i) q += Qp[i];
    float gnorm = sqrtf(G) * (float)PS;
    float pnorm = sqrtf(q);
    d_cos[bp] = D / fmaxf(gnorm * pnorm, 1e-8f);
  }
}

// ------------------------------------------------------- apply mask (covered)
// Block = (b, pp, kh-pair, channel-half of 128). Warp 0 computes
// argmax/argmin of cos to pick the source patch. Depth-2 cp.async pipeline:
// issue gathers for both kh rows up front (two commit groups), then
// wait_group 1 -> barrier -> compute kh0 (x LDG batched + LDS + FFMA + STG)
// while kh1's gather is still in flight; wait_group 0 -> barrier -> compute
// kh1. Staging layout per stage: word(kw,cl) = kw*SBS + (cl^swz(kw)) ->
// STS.128-equivalent cp.async 16B, conflict-free; read side ~1.4-way.
__global__ __launch_bounds__(512, 3) void k_apply(const float* __restrict__ x,
                                                  float* __restrict__ out) {
  extern __shared__ float sbuf[];    // 2 stages x 27.5 KB = 55 KB dynamic
  __shared__ int s_sp;
  int lin = blockIdx.x;
  int chalf = lin & 1;
  int khp = (lin >> 1) % 26;         // kh pair
  int pp = ((lin >> 1) / 26) % P_;
  int b  = lin / (2 * 26 * P_);
  int ph = pp / NW, pw = pp - ph * NW;
  int t = threadIdx.x;
  int c0 = chalf * 128;

  if (t < 32) {                      // warp 0: argmax/argmin over 81 cos
    int lane = t;
    float vmax = -CUDART_INF_F, vmin = CUDART_INF_F;
    int imax = -1, imin = -1;
    #pragma unroll
    for (int k = 0; k < 3; ++k) {
      int i = lane + 32 * k;
      if (i < P_) {
        float cv = d_cos[b * P_ + i];
        if (cv > vmax || (cv == vmax && i < imax)) { vmax = cv; imax = i; }
        if (cv < vmin || (cv == vmin && i < imin)) { vmin = cv; imin = i; }
      }
    }
    #pragma unroll
    for (int o = 16; o > 0; o >>= 1) {
      float ov = __shfl_down_sync(0xffffffffu, vmax, o);
      int   oi = __shfl_down_sync(0xffffffffu, imax, o);
      if (ov > vmax || (ov == vmax && oi < imax)) { vmax = ov; imax = oi; }
      float nv = __shfl_down_sync(0xffffffffu, vmin, o);
      int   ni = __shfl_down_sync(0xffffffffu, imin, o);
      if (nv < vmin || (nv == vmin && ni < imin)) { vmin = nv; imin = ni; }
    }
    if (lane == 0) s_sp = (pp == imax) ? imin : pp;
  }
  __syncthreads();
  int sp = s_sp;
  int sph = sp / NW, spw = sp - sph * NW;

  const float* src = x + (size_t)b * C_ * PLANE + (size_t)(sph * PS) * W_ + spw * PS;
  int wb = pw * PS;
  uint32_t sb_u32 = (uint32_t)__cvta_generic_to_shared(sbuf);

  // Issue gathers for both kh rows (source-linear, coalesced; m = mbase + i
  // is consecutive source addresses, no row/chan straddle)
  #pragma unroll
  for (int s = 0; s < 2; ++s) {
    int kh = khp * 2 + s;
    int mbase = kh * PS * 256 + c0;
    uint32_t stage = sb_u32 + (uint32_t)(s * STGF) * 4u;
    #pragma unroll
    for (int k = 0; k < 4; ++k) {
      int i4 = t + 512 * k;
      if (i4 < 1664) {
        int i = i4 << 2;
        int kw = i >> 7;
        int cl = i & 127;
        int m = mbase + kw * 256 + cl;
        int cs  = m / QQ;
        int r   = m - cs * QQ;
        int khs = r / PS;
        int kws = r - khs * PS;
        int si = kw * SBS + (cl ^ swz(kw));
        cp16(stage + (si << 2), src + (size_t)cs * PLANE + khs * W_ + kws);
      }
    }
    asm volatile("cp.async.commit_group;\n" ::: "memory");
  }

  // Compute stages
  #pragma unroll
  for (int s = 0; s < 2; ++s) {
    if (s == 0) asm volatile("cp.async.wait_group 1;\n" ::: "memory");
    else        asm volatile("cp.async.wait_group 0;\n" ::: "memory");
    __syncthreads();
    int kh = khp * 2 + s;
    int h  = ph * PS + kh;
    const float* st = sbuf + s * STGF;
    #pragma unroll
    for (int k = 0; k < 4; ++k) {
      int i4 = t + 512 * k;
      if (i4 < 1664) {
        int col_ = i4 / 13;
        int kw0  = (i4 - col_ * 13) << 2;
        uint32_t off = (uint32_t)(((b * C_ + c0 + col_) * H_ + h) * W_ + wb + kw0);
        float4 xv = *reinterpret_cast<const float4*>(x + off);
        float m0v = st[(kw0    ) * SBS + (col_ ^ swz(kw0    ))];
        float m1v = st[(kw0 + 1) * SBS + (col_ ^ swz(kw0 + 1))];
        float m2v = st[(kw0 + 2) * SBS + (col_ ^ swz(kw0 + 2))];
        float m3v = st[(kw0 + 3) * SBS + (col_ ^ swz(kw0 + 3))];
        float4 ov;
        ov.x = m0v * xv.x;
        ov.y = m1v * xv.y;
        ov.z = m2v * xv.z;
        ov.w = m3v * xv.w;
        *reinterpret_cast<float4*>(out + off) = ov;
      }
    }
  }
}

// ------------------------------------------------------------ zero the border
__global__ __launch_bounds__(256) void k_border_out(float* __restrict__ out) {
  int plane = blockIdx.y;
  size_t pb = (size_t)plane * PLANE;
  float4 z = make_float4(0.f, 0.f, 0.f, 0.f);
  for (int i = blockIdx.x * blockDim.x + threadIdx.x; i < 10780;
       i += gridDim.x * blockDim.x) {
    size_t off;
    if (i < 5148) { int r = i / 11; int cq = i - r * 11;
                    off = pb + (size_t)r * W_ + 468 + (cq << 2); }
    else          { int j = i - 5148; int r = j >> 7; int cq = j & 127;
                    off = pb + (size_t)(468 + r) * W_ + (cq << 2); }
    *reinterpret_cast<float4*>(out + off) = z;
  }
}

extern "C" void kernel_launch(void* const* d_in, const int* in_sizes, int n_in,
                              void* d_out, int out_size) {
  (void)in_sizes; (void)n_in; (void)out_size;
  const float* x = (const float*)d_in[0];
  float* out = (float*)d_out;

  cudaFuncSetAttribute(k_apply, cudaFuncAttributeMaxDynamicSharedMemorySize,
                       2 * STGF * sizeof(float));

  k_stats<<<B_ * P_ * 16, 256>>>(x);
  k_border_g<<<dim3(2, B_ * C_), 256>>>(x);
  k_cos<<<B_ * P_, 256>>>();
  k_apply<<<B_ * P_ * 26 * 2, 512, 2 * STGF * sizeof(float)>>>(x, out); // slot 4
  k_border_out<<<dim3(11, B_ * C_), 256>>>(out);
}

// round 17
// speedup vs baseline: 1.0360x; 1.0346x over previous
#include <cuda_runtime.h>
#include <cstdint>
#include <cstddef>
#include <math_constants.h>

#define B_    2
#define C_    256
#define H_    512
#define W_    512
#define PS    52
#define NH    9
#define NW    9
#define P_    81
#define QQ    2704         // PS*PS
#define PLANE (H_*W_)      // 262144

#define SBS   132          // staging stride (mult of 4; +XOR swizzle)

#define STATS_BLOCKS  (B_ * P_ * 16)        // 2592
#define BG_BLOCKS     (B_ * C_ * 2)         // 1024
#define APPLY_BLOCKS  (B_ * P_ * PS * 2)    // 16848
#define BO_BLOCKS     (B_ * C_)             // 512

// Scratch (device globals: no allocations allowed)
__device__ float d_gp[B_*P_*256];       // per (b,pp) per-channel sums (covered)
__device__ float d_gb2[B_*C_*2];        // per-plane border sums (2 partials)
__device__ float d_S16[B_*P_*16*256];   // per (b,pp,cg) partial weighted sums
__device__ float d_Q16[B_*P_*16];       // per (b,pp,cg) partial sumsq
__device__ float d_cos[B_*P_];

__device__ __forceinline__ float warpReduce(float v) {
  #pragma unroll
  for (int o = 16; o > 0; o >>= 1) v += __shfl_down_sync(0xffffffffu, v, o);
  return v;
}

__device__ __forceinline__ int swz(int kw) {   // XOR swizzle, mult of 4
  return ((kw + (kw >> 2)) & 7) << 2;
}

__device__ __forceinline__ void cp16(uint32_t saddr, const void* gaddr) {
  asm volatile("cp.async.cg.shared.global [%0], [%1], 16;\n"
               :: "r"(saddr), "l"(gaddr));
}

// --------------------- per-patch stats (covered) + border GAP (fused kernel)
// bid <  STATS_BLOCKS: block = (b, pp, channel-group of 16). 4 lane-groups of
//   64; lane u of group g owns bins 4u..4u+3: reads float4 at
//   q = ((4u-144c)&255) + 256*j (widx of element q+k is 4u+k; kw == 0 mod 4
//   so no source-row straddle). Bins in registers -> smem merge. No atomics.
// bid >= STATS_BLOCKS: border GAP partial (plane, half).
__global__ __launch_bounds__(256) void k_stats_bg(const float* __restrict__ x) {
  __shared__ float4 sb4[4 * 64];     // [group][u] bins 4u..4u+3
  __shared__ float qred[8];
  __shared__ float sm_g[8 * 4];      // [warp][cc] per-warp channel partials
  int bid = blockIdx.x;
  int t = threadIdx.x;
  int lane = t & 31, warp = t >> 5;

  if (bid >= STATS_BLOCKS) {         // ---- border GAP path
    int idx = bid - STATS_BLOCKS;
    int plane = idx >> 1;            // 0..511
    int half = idx & 1;
    const float* pb = x + (size_t)plane * PLANE;
    float s = 0.f;
    #pragma unroll 4
    for (int j = half * 256 + t; j < 43120; j += 512) {
      int r, col;
      if (j < 20592) { r = j / 44; col = 468 + (j - r * 44); }
      else           { int j2 = j - 20592; r = 468 + (j2 >> 9); col = j2 & 511; }
      s += pb[(size_t)r * W_ + col];
    }
    s = warpReduce(s);
    if (lane == 0) qred[warp] = s;
    __syncthreads();
    if (warp == 0) {
      float v = (lane < 8) ? qred[lane] : 0.f;
      v = warpReduce(v);
      if (lane == 0) d_gb2[plane * 2 + half] = v;
    }
    return;
  }

  // ---- stats path
  int cg = bid & 15;                 // C_/CG == 16 groups
  int pp = (bid >> 4) % P_;
  int b  = bid / (16 * P_);
  int ph = pp / NW, pw = pp - ph * NW;
  int g = t >> 6;                    // lane-group 0..3
  int u = t & 63;                    // 0..63, owns bins 4u..4u+3

  const float* pbase = x + (size_t)b * C_ * PLANE + (size_t)(ph * PS) * W_ + pw * PS;

  float a0 = 0.f, a1 = 0.f, a2 = 0.f, a3 = 0.f;  // bins 4u..4u+3
  float qacc = 0.f;                               // sum of squares
  #pragma unroll 1
  for (int cc = 0; cc < 4; ++cc) {
    int c = cg * 16 + g * 4 + cc;
    const float* cb = pbase + (size_t)c * PLANE;
    int q0 = (4 * u - 144 * c) & 255;
    float csum = 0.f;
    #pragma unroll
    for (int j = 0; j < 11; ++j) {
      int q = q0 + 256 * j;
      if (q < QQ) {
        int kh = q / PS;
        int kw = q - kh * PS;
        float4 v = *reinterpret_cast<const float4*>(cb + kh * W_ + kw);
        a0 += v.x; a1 += v.y; a2 += v.z; a3 += v.w;
        csum += (v.x + v.y) + (v.z + v.w);
        qacc = fmaf(v.x, v.x, qacc);
        qacc = fmaf(v.y, v.y, qacc);
        qacc = fmaf(v.z, v.z, qacc);
        qacc = fmaf(v.w, v.w, qacc);
      }
    }
    csum = warpReduce(csum);
    if (lane == 0) sm_g[warp * 4 + cc] = csum;   // two warps per group
  }
  sb4[g * 64 + u] = make_float4(a0, a1, a2, a3);

  qacc = warpReduce(qacc);
  if (lane == 0) qred[warp] = qacc;
  __syncthreads();

  // merge the 4 group-copies of bin t and store
  const float* sb = reinterpret_cast<const float*>(sb4);
  float S = sb[t] + sb[256 + t] + sb[512 + t] + sb[768 + t];
  d_S16[((size_t)(b * P_ + pp) * 16 + cg) * 256 + t] = S;

  if (t < 16) {                      // channel c = cg*16 + t, t = g*4+cc
    int gg = t >> 2, cc = t & 3;
    float cs2 = sm_g[(2 * gg) * 4 + cc] + sm_g[(2 * gg + 1) * 4 + cc];
    d_gp[(b * P_ + pp) * 256 + cg * 16 + t] = cs2;  // unique writer
  }
  if (warp == 0) {
    float v = (lane < 8) ? qred[lane] : 0.f;
    v = warpReduce(v);
    if (lane == 0) d_Q16[(b * P_ + pp) * 16 + cg] = v;
  }
}

// --------------------------------------------- cosine per patch (grid 2*81)
// Folds the gsum reduction (81 covered partials + 2 border partials).
__global__ __launch_bounds__(256) void k_cos() {
  int bp = blockIdx.x;               // b*81 + pp
  int b = bp / P_;
  int t = threadIdx.x;
  int lane = t & 31, warp = t >> 5;

  float gs = d_gb2[(b * C_ + t) * 2] + d_gb2[(b * C_ + t) * 2 + 1];
  const float* gp = d_gp + (size_t)b * P_ * 256 + t;
  #pragma unroll
  for (int i = 0; i < P_; ++i) gs += gp[i * 256];
  float g = gs * (1.0f / (float)PLANE);

  float s = 0.f;
  const float* Sp = d_S16 + (size_t)bp * 16 * 256 + t;
  #pragma unroll
  for (int cg = 0; cg < 16; ++cg) s += Sp[cg * 256];

  float dotv = s * g;
  float gg = g * g;
  __shared__ float rd[8], rg[8];
  dotv = warpReduce(dotv);
  gg = warpReduce(gg);
  if (lane == 0) { rd[warp] = dotv; rg[warp] = gg; }
  __syncthreads();
  if (t == 0) {
    float D = 0.f, G = 0.f;
    #pragma unroll
    for (int i = 0; i < 8; ++i) { D += rd[i]; G += rg[i]; }
    float q = 0.f;
    const float* Qp = d_Q16 + bp * 16;
    #pragma unroll
    for (int i = 0; i < 16; ++i) q += Qp[i];
    float gnorm = sqrtf(G) * (float)PS;
    float pnorm = sqrtf(q);
    d_cos[bp] = D / fmaxf(gnorm * pnorm, 1e-8f);
  }
}

// ------------------------- apply mask (covered) + border zero (fused kernel)
// lin <  APPLY_BLOCKS: block = (b, pp, kh, channel-half of 128). Warp 0
//   computes argmax/argmin of cos (tie -> lower index). Phase 1: gather via
//   cp.async.cg into swizzled smem (m = (kh*52+kw)*256+c is consecutive
//   source addresses; no row/channel straddle) + cross-barrier prefetch of
//   the aligned multiplicand float4s. Phase 2: LDS+FFMA+STG only.
// lin >= APPLY_BLOCKS: zero the uncovered border of one output plane.
__global__ __launch_bounds__(512, 3) void k_apply_bo(const float* __restrict__ x,
                                                     float* __restrict__ out) {
  __shared__ float sbuf[PS * SBS];   // 27.5 KB
  __shared__ int s_sp;
  int lin = blockIdx.x;
  int t = threadIdx.x;

  if (lin >= APPLY_BLOCKS) {         // ---- border-zero path
    int plane = lin - APPLY_BLOCKS;  // 0..511
    size_t pb = (size_t)plane * PLANE;
    float4 z = make_float4(0.f, 0.f, 0.f, 0.f);
    // R1: 468 rows x 11 quads; R2: 44 rows x 128 quads -> 10780 quads
    for (int i = t; i < 10780; i += 512) {
      size_t off;
      if (i < 5148) { int r = i / 11; int cq = i - r * 11;
                      off = pb + (size_t)r * W_ + 468 + (cq << 2); }
      else          { int j = i - 5148; int r = j >> 7; int cq = j & 127;
                      off = pb + (size_t)(468 + r) * W_ + (cq << 2); }
      *reinterpret_cast<float4*>(out + off) = z;
    }
    return;
  }

  int chalf = lin & 1;
  int kh = (lin >> 1) % PS;
  int pp = ((lin >> 1) / PS) % P_;
  int b  = lin / (2 * PS * P_);
  int ph = pp / NW, pw = pp - ph * NW;
  int c0 = chalf * 128;

  if (t < 32) {                      // warp 0: argmax/argmin over 81 cos
    int lane = t;
    float vmax = -CUDART_INF_F, vmin = CUDART_INF_F;
    int imax = -1, imin = -1;
    #pragma unroll
    for (int k = 0; k < 3; ++k) {
      int i = lane + 32 * k;
      if (i < P_) {
        float cv = d_cos[b * P_ + i];
        if (cv > vmax || (cv == vmax && i < imax)) { vmax = cv; imax = i; }
        if (cv < vmin || (cv == vmin && i < imin)) { vmin = cv; imin = i; }
      }
    }
    #pragma unroll
    for (int o = 16; o > 0; o >>= 1) {
      float ov = __shfl_down_sync(0xffffffffu, vmax, o);
      int   oi = __shfl_down_sync(0xffffffffu, imax, o);
      if (ov > vmax || (ov == vmax && oi < imax)) { vmax = ov; imax = oi; }
      float nv = __shfl_down_sync(0xffffffffu, vmin, o);
      int   ni = __shfl_down_sync(0xffffffffu, imin, o);
      if (nv < vmin || (nv == vmin && ni < imin)) { vmin = nv; imin = ni; }
    }
    if (lane == 0) s_sp = (pp == imax) ? imin : pp;
  }
  __syncthreads();
  int sp = s_sp;
  int sph = sp / NW, spw = sp - sph * NW;

  const float* xb = x + (size_t)b * C_ * PLANE;
  const float* src = xb + (size_t)(sph * PS) * W_ + spw * PS;
  int mbase = kh * PS * 256 + c0;
  int h  = ph * PS + kh;
  int wb = pw * PS;
  uint32_t sb_u32 = (uint32_t)__cvta_generic_to_shared(sbuf);

  // Phase 1a: gather 1664 float4 via cp.async (source-linear, coalesced)
  #pragma unroll
  for (int k = 0; k < 4; ++k) {
    int i4 = t + 512 * k;
    if (i4 < 1664) {
      int i = i4 << 2;
      int kw = i >> 7;
      int cl = i & 127;
      int m = mbase + kw * 256 + cl;
      int cs  = m / QQ;
      int r   = m - cs * QQ;
      int khs = r / PS;
      int kws = r - khs * PS;
      int si = kw * SBS + (cl ^ swz(kw));
      cp16(sb_u32 + (si << 2), src + (size_t)cs * PLANE + khs * W_ + kws);
    }
  }
  asm volatile("cp.async.commit_group;\n" ::: "memory");

  // Phase 1b: prefetch multiplicand float4s (independent of smem)
  float4 pre[4];
  #pragma unroll
  for (int k = 0; k < 4; ++k) {
    int i4 = t + 512 * k;
    if (i4 < 1664) {
      int col_ = i4 / 13;
      int kw0  = (i4 - col_ * 13) << 2;
      size_t off = ((size_t)(b * C_ + c0 + col_) * H_ + h) * W_ + wb + kw0;
      pre[k] = *reinterpret_cast<const float4*>(x + off);
    }
  }

  asm volatile("cp.async.wait_group 0;\n" ::: "memory");
  __syncthreads();

  // Phase 2: smem reads + FFMA + coalesced float4 stores
  #pragma unroll
  for (int k = 0; k < 4; ++k) {
    int i4 = t + 512 * k;
    if (i4 < 1664) {
      int col_ = i4 / 13;
      int kw0  = (i4 - col_ * 13) << 2;
      float m0v = sbuf[(kw0    ) * SBS + (col_ ^ swz(kw0    ))];
      float m1v = sbuf[(kw0 + 1) * SBS + (col_ ^ swz(kw0 + 1))];
      float m2v = sbuf[(kw0 + 2) * SBS + (col_ ^ swz(kw0 + 2))];
      float m3v = sbuf[(kw0 + 3) * SBS + (col_ ^ swz(kw0 + 3))];
      size_t off = ((size_t)(b * C_ + c0 + col_) * H_ + h) * W_ + wb + kw0;
      float4 ov;
      ov.x = m0v * pre[k].x;
      ov.y = m1v * pre[k].y;
      ov.z = m2v * pre[k].z;
      ov.w = m3v * pre[k].w;
      *reinterpret_cast<float4*>(out + off) = ov;
    }
  }
}

extern "C" void kernel_launch(void* const* d_in, const int* in_sizes, int n_in,
                              void* d_out, int out_size) {
  (void)in_sizes; (void)n_in; (void)out_size;
  const float* x = (const float*)d_in[0];
  float* out = (float*)d_out;

  k_stats_bg<<<STATS_BLOCKS + BG_BLOCKS, 256>>>(x);
  k_cos<<<B_ * P_, 256>>>();
  k_apply_bo<<<APPLY_BLOCKS + BO_BLOCKS, 512>>>(x, out);
}